// round 1
// baseline (speedup 1.0000x reference)
#include <cuda_runtime.h>
#include <math.h>

#define N 8192
#define D 128
#define NB 64                 // N / 128
#define ENC_NEGINF 0x007FFFFFu
#define NEGINF __int_as_float(0xff800000)

// ---------------- scratch (static __device__, no allocation) ----------------
__device__ unsigned g_rowmax[N];   // encoded-float max_{j!=i} (2*G_ij - sq_j)
__device__ float    g_sq[N];
__device__ float    g_lse[N];
__device__ int      g_flaglist[N];
__device__ int      g_flagcnt;

// ---------------- helpers ----------------
__device__ __forceinline__ float softplus_var(const float* __restrict__ phi) {
    float p = *phi;
    return (p > 20.f) ? p : log1pf(expf(p));
}
// order-preserving float<->uint encoding for atomicMax
__device__ __forceinline__ unsigned fenc(float f) {
    unsigned u = __float_as_uint(f);
    return (u & 0x80000000u) ? ~u : (u | 0x80000000u);
}
__device__ __forceinline__ float fdec(unsigned e) {
    return (e & 0x80000000u) ? __uint_as_float(e & 0x7FFFFFFFu)
                             : __uint_as_float(~e);
}

// ---------------- K1: out = x + var*noise ; sq[i] ; init scratch ----------------
__global__ void k1_rows(const float* __restrict__ x, const float* __restrict__ phi,
                        const float* __restrict__ noise, float* __restrict__ out) {
    int r = blockIdx.x;
    int t = threadIdx.x;
    float var = softplus_var(phi);
    float xv = x[(size_t)r * D + t];
    float nv = noise[(size_t)r * D + t];
    out[(size_t)r * D + t] = xv + var * nv;

    float s = xv * xv;
    #pragma unroll
    for (int o = 16; o; o >>= 1) s += __shfl_xor_sync(0xffffffffu, s, o);
    __shared__ float ws[4];
    if ((t & 31) == 0) ws[t >> 5] = s;
    __syncthreads();
    if (t == 0) {
        g_sq[r] = ws[0] + ws[1] + ws[2] + ws[3];
        g_rowmax[r] = ENC_NEGINF;
        if (r == 0) g_flagcnt = 0;
    }
}

// ---------------- K2: upper-triangular Gram tiles + off-diagonal row-max ----------------
#define BKK 16
#define SPAD 4
__global__ __launch_bounds__(256, 2)
void k2_gram(const float* __restrict__ x) {
    __shared__ float As[BKK][128 + SPAD];
    __shared__ float Bs[BKK][128 + SPAD];
    __shared__ float asq[128], bsq[128];
    __shared__ float red[128][17];

    // triangular block decode: b -> (bi, bj), bi <= bj
    int b = blockIdx.x;
    int bi = 0, rem = b;
    while (rem >= NB - bi) { rem -= NB - bi; bi++; }
    int bj = bi + rem;

    int tid = threadIdx.x;
    int tx = tid & 15, ty = tid >> 4;

    if (tid < 128) asq[tid] = g_sq[bi * 128 + tid];
    else           bsq[tid - 128] = g_sq[bj * 128 + tid - 128];

    const float* Abase = x + (size_t)bi * 128 * D;
    const float* Bbase = x + (size_t)bj * 128 * D;

    float acc[8][8];
    #pragma unroll
    for (int i = 0; i < 8; i++)
        #pragma unroll
        for (int j = 0; j < 8; j++) acc[i][j] = 0.f;

    for (int k0 = 0; k0 < D; k0 += BKK) {
        __syncthreads();
        #pragma unroll
        for (int q = tid; q < 512; q += 256) {
            int row = q >> 2;
            int kq  = (q & 3) << 2;
            float4 va = *(const float4*)(Abase + (size_t)row * D + k0 + kq);
            As[kq + 0][row] = va.x; As[kq + 1][row] = va.y;
            As[kq + 2][row] = va.z; As[kq + 3][row] = va.w;
            float4 vb = *(const float4*)(Bbase + (size_t)row * D + k0 + kq);
            Bs[kq + 0][row] = vb.x; Bs[kq + 1][row] = vb.y;
            Bs[kq + 2][row] = vb.z; Bs[kq + 3][row] = vb.w;
        }
        __syncthreads();
        #pragma unroll
        for (int kk = 0; kk < BKK; kk++) {
            float a[8], bb[8];
            const float4* ap = (const float4*)&As[kk][ty * 8];
            const float4* bp = (const float4*)&Bs[kk][tx * 8];
            float4 a0 = ap[0], a1 = ap[1];
            float4 b0 = bp[0], b1 = bp[1];
            a[0]=a0.x; a[1]=a0.y; a[2]=a0.z; a[3]=a0.w;
            a[4]=a1.x; a[5]=a1.y; a[6]=a1.z; a[7]=a1.w;
            bb[0]=b0.x; bb[1]=b0.y; bb[2]=b0.z; bb[3]=b0.w;
            bb[4]=b1.x; bb[5]=b1.y; bb[6]=b1.z; bb[7]=b1.w;
            #pragma unroll
            for (int y = 0; y < 8; y++)
                #pragma unroll
                for (int xx = 0; xx < 8; xx++)
                    acc[y][xx] += a[y] * bb[xx];
        }
    }

    bool diag = (bi == bj);

    // -------- row-direction maxes: rows of block bi, max over cols of block bj --------
    #pragma unroll
    for (int y = 0; y < 8; y++) {
        int rl = ty * 8 + y;
        float rm = NEGINF;
        #pragma unroll
        for (int xx = 0; xx < 8; xx++) {
            int cl = tx * 8 + xx;
            float v = 2.f * acc[y][xx] - bsq[cl];
            if (diag && rl == cl) v = NEGINF;
            rm = fmaxf(rm, v);
        }
        red[rl][tx] = rm;
    }
    __syncthreads();
    if (tid < 128) {
        float m = NEGINF;
        #pragma unroll
        for (int t = 0; t < 16; t++) m = fmaxf(m, red[tid][t]);
        atomicMax(&g_rowmax[bi * 128 + tid], fenc(m));
    }
    __syncthreads();

    // -------- col-direction maxes: rows of block bj, max over rows of block bi --------
    #pragma unroll
    for (int xx = 0; xx < 8; xx++) {
        int cl = tx * 8 + xx;
        float cm = NEGINF;
        #pragma unroll
        for (int y = 0; y < 8; y++) {
            int rl = ty * 8 + y;
            float v = 2.f * acc[y][xx] - asq[rl];
            if (diag && rl == cl) v = NEGINF;
            cm = fmaxf(cm, v);
        }
        red[cl][ty] = cm;
    }
    __syncthreads();
    if (tid < 128) {
        float m = NEGINF;
        #pragma unroll
        for (int t = 0; t < 16; t++) m = fmaxf(m, red[tid][t]);
        atomicMax(&g_rowmax[bj * 128 + tid], fenc(m));
    }
}

// ---------------- K3: screen rows; default lse = 0 ----------------
__global__ void k3_screen(const float* __restrict__ phi) {
    int i = blockIdx.x * blockDim.x + threadIdx.x;
    if (i >= N) return;
    float var = softplus_var(phi);
    float m = fdec(g_rowmax[i]);
    // z_max over off-diagonal terms, with the d2>=0 clamp applied
    float zmax = fminf((m - g_sq[i]) * (0.5f / var), 0.f);
    g_lse[i] = 0.f;   // screened rows: fp32 logsumexp == log(1 + <eps) == 0
    if (zmax > -35.f) {
        int k = atomicAdd(&g_flagcnt, 1);
        g_flaglist[k] = i;
    }
}

// ---------------- K4: exact fallback for flagged rows ----------------
__global__ void k4_exact(const float* __restrict__ x, const float* __restrict__ phi) {
    __shared__ float xi[D];
    __shared__ float part[256];
    int nf = g_flagcnt;
    float var = softplus_var(phi);
    float half_inv = 0.5f / var;
    for (int f = blockIdx.x; f < nf; f += gridDim.x) {
        int i = g_flaglist[f];
        if (threadIdx.x < D) xi[threadIdx.x] = x[(size_t)i * D + threadIdx.x];
        __syncthreads();
        float sqi = g_sq[i];
        float s = 0.f;
        for (int j = threadIdx.x; j < N; j += blockDim.x) {
            const float* xj = x + (size_t)j * D;
            float dot = 0.f;
            #pragma unroll 8
            for (int k = 0; k < D; k++) dot += xi[k] * xj[k];
            float d2 = fmaxf(sqi + g_sq[j] - 2.f * dot, 0.f);
            s += expf(-d2 * half_inv);
        }
        part[threadIdx.x] = s;
        __syncthreads();
        for (int o = 128; o; o >>= 1) {
            if (threadIdx.x < o) part[threadIdx.x] += part[threadIdx.x + o];
            __syncthreads();
        }
        if (threadIdx.x == 0) g_lse[i] = logf(part[0]);
        __syncthreads();
    }
}

// ---------------- K5: reduce -> IXT ----------------
__global__ void k5_reduce(float* __restrict__ out_scalar) {
    __shared__ float part[256];
    float s = 0.f;
    for (int i = threadIdx.x; i < N; i += 256) s += g_lse[i];
    part[threadIdx.x] = s;
    __syncthreads();
    for (int o = 128; o; o >>= 1) {
        if (threadIdx.x < o) part[threadIdx.x] += part[threadIdx.x + o];
        __syncthreads();
    }
    if (threadIdx.x == 0) {
        float kde = part[0] / (float)N;
        float ixt = (logf((float)N) - kde) * 1.4426950408889634f;
        *out_scalar = ixt;
    }
}

// ---------------- launch ----------------
extern "C" void kernel_launch(void* const* d_in, const int* in_sizes, int n_in,
                              void* d_out, int out_size) {
    const float* x     = (const float*)d_in[0];
    const float* phi   = (const float*)d_in[1];
    const float* noise = (const float*)d_in[2];
    float* out = (float*)d_out;

    k1_rows<<<N, 128>>>(x, phi, noise, out);
    k2_gram<<<NB * (NB + 1) / 2, 256>>>(x);
    k3_screen<<<(N + 255) / 256, 256>>>(phi);
    k4_exact<<<64, 256>>>(x, phi);
    k5_reduce<<<1, 256>>>(out + out_size - 1);
}

// round 3
// speedup vs baseline: 3.7851x; 3.7851x over previous
#include <cuda_runtime.h>
#include <cuda_bf16.h>
#include <math.h>
#include <stdint.h>

#define N 8192
#define D 128
#define NB 64                 // N / 128
#define ENC_NEGINF 0x007FFFFFu
#define NEGINF __int_as_float(0xff800000)

// ---------------- scratch (static __device__, no allocation) ----------------
__device__ unsigned g_rowmax[N];   // encoded-float max_{j!=i} (2*G_ij - sq_j)
__device__ float    g_sq[N];
__device__ float    g_lse[N];
__device__ int      g_flaglist[N];
__device__ int      g_flagcnt;
__device__ __align__(16) __nv_bfloat16 g_xb[N * D];   // bf16 copy of x (2 MB)

// ---------------- helpers ----------------
__device__ __forceinline__ uint32_t smem_u32(const void* p) {
    uint32_t a;
    asm("{ .reg .u64 t; cvta.to.shared.u64 t, %1; cvt.u32.u64 %0, t; }" : "=r"(a) : "l"(p));
    return a;
}
__device__ __forceinline__ float softplus_var(const float* __restrict__ phi) {
    float p = *phi;
    return (p > 20.f) ? p : log1pf(expf(p));
}
// order-preserving float<->uint encoding for atomicMax
__device__ __forceinline__ unsigned fenc(float f) {
    unsigned u = __float_as_uint(f);
    return (u & 0x80000000u) ? ~u : (u | 0x80000000u);
}
__device__ __forceinline__ float fdec(unsigned e) {
    return (e & 0x80000000u) ? __uint_as_float(e & 0x7FFFFFFFu)
                             : __uint_as_float(~e);
}

__device__ __forceinline__ void ldsm_x4(uint32_t& r0, uint32_t& r1, uint32_t& r2, uint32_t& r3,
                                        uint32_t addr) {
    asm volatile("ldmatrix.sync.aligned.m8n8.x4.shared.b16 {%0,%1,%2,%3}, [%4];"
                 : "=r"(r0), "=r"(r1), "=r"(r2), "=r"(r3) : "r"(addr));
}
__device__ __forceinline__ void ldsm_x2(uint32_t& r0, uint32_t& r1, uint32_t addr) {
    asm volatile("ldmatrix.sync.aligned.m8n8.x2.shared.b16 {%0,%1}, [%2];"
                 : "=r"(r0), "=r"(r1) : "r"(addr));
}
__device__ __forceinline__ void mma_bf16(float* d, const uint32_t* a, const uint32_t* b) {
    asm volatile(
        "mma.sync.aligned.m16n8k16.row.col.f32.bf16.bf16.f32 "
        "{%0,%1,%2,%3}, {%4,%5,%6,%7}, {%8,%9}, {%0,%1,%2,%3};"
        : "+f"(d[0]), "+f"(d[1]), "+f"(d[2]), "+f"(d[3])
        : "r"(a[0]), "r"(a[1]), "r"(a[2]), "r"(a[3]), "r"(b[0]), "r"(b[1]));
}

// ---------------- K1: out = x + var*noise ; sq[i] ; bf16 copy ; init ----------------
__global__ void k1_rows(const float* __restrict__ x, const float* __restrict__ phi,
                        const float* __restrict__ noise, float* __restrict__ out) {
    int r = blockIdx.x;
    int t = threadIdx.x;
    float var = softplus_var(phi);
    float xv = x[(size_t)r * D + t];
    float nv = noise[(size_t)r * D + t];
    out[(size_t)r * D + t] = xv + var * nv;
    g_xb[(size_t)r * D + t] = __float2bfloat16(xv);

    float s = xv * xv;
    #pragma unroll
    for (int o = 16; o; o >>= 1) s += __shfl_xor_sync(0xffffffffu, s, o);
    __shared__ float ws[4];
    if ((t & 31) == 0) ws[t >> 5] = s;
    __syncthreads();
    if (t == 0) {
        g_sq[r] = ws[0] + ws[1] + ws[2] + ws[3];
        g_rowmax[r] = ENC_NEGINF;
        if (r == 0) g_flagcnt = 0;
    }
}

// ---------------- K2: bf16 mma.sync Gram, upper triangle, row/col maxes ----------------
// Padded smem tile: 128 rows x 136 bf16 (272 B/row) -> conflict-free ldmatrix
#define ROWB 272
#define SM_A    0
#define SM_B    34816
#define SM_ASQ  69632
#define SM_BSQ  70144
#define SM_RRED 70656                    // float[128][4]
#define SM_CRED 72704                    // float[128][2]
#define SM_TOTAL 73728

__global__ __launch_bounds__(256, 2)
void k2_gram_mma() {
    extern __shared__ char sm[];
    uint32_t sb = smem_u32(sm);
    int tid = threadIdx.x;
    int wid = tid >> 5, lane = tid & 31;
    int warp_m = wid >> 2;          // 0..1  (64-row band)
    int warp_n = wid & 3;           // 0..3  (32-col band)

    // triangular block decode: b -> (bi, bj), bi <= bj
    int b = blockIdx.x;
    int bi = 0, rem = b;
    while (rem >= NB - bi) { rem -= NB - bi; bi++; }
    int bj = bi + rem;
    bool diag = (bi == bj);

    // ---- load tiles (bf16) ----
    const uint4* Ag = (const uint4*)(g_xb + (size_t)bi * 128 * D);
    const uint4* Bg = (const uint4*)(g_xb + (size_t)bj * 128 * D);
    #pragma unroll
    for (int it = 0; it < 8; it++) {
        int q = it * 256 + tid;             // 0..2047
        int row = q >> 4, seg = q & 15;
        uint32_t off = (uint32_t)row * ROWB + (uint32_t)seg * 16;
        *(uint4*)(sm + SM_A + off) = Ag[q];
        *(uint4*)(sm + SM_B + off) = Bg[q];
    }
    float* asq = (float*)(sm + SM_ASQ);
    float* bsq = (float*)(sm + SM_BSQ);
    if (tid < 128) asq[tid] = g_sq[bi * 128 + tid];
    else           bsq[tid - 128] = g_sq[bj * 128 + tid - 128];
    __syncthreads();

    // ---- mma mainloop: warp tile 64x32, K=128 ----
    int R0 = warp_m * 64;
    int C0 = warp_n * 32;
    float acc[4][4][4];
    #pragma unroll
    for (int mt = 0; mt < 4; mt++)
        #pragma unroll
        for (int nt = 0; nt < 4; nt++)
            #pragma unroll
            for (int r = 0; r < 4; r++) acc[mt][nt][r] = 0.f;

    // ldmatrix lane addresses
    uint32_t a_row = (uint32_t)(R0 + (lane & 15));
    uint32_t a_kb  = (uint32_t)((lane >> 4) * 16);
    uint32_t b_row = (uint32_t)(C0 + (lane & 7));
    uint32_t b_kb  = (uint32_t)(((lane >> 3) & 1) * 16);

    #pragma unroll
    for (int kt = 0; kt < 8; kt++) {
        uint32_t kbase = (uint32_t)kt * 32;   // 16 bf16 = 32 bytes per k-step
        uint32_t af[4][4];
        #pragma unroll
        for (int mt = 0; mt < 4; mt++) {
            uint32_t addr = sb + SM_A + (a_row + mt * 16) * ROWB + kbase + a_kb;
            ldsm_x4(af[mt][0], af[mt][1], af[mt][2], af[mt][3], addr);
        }
        uint32_t bf[4][2];
        #pragma unroll
        for (int nt = 0; nt < 4; nt++) {
            uint32_t addr = sb + SM_B + (b_row + nt * 8) * ROWB + kbase + b_kb;
            ldsm_x2(bf[nt][0], bf[nt][1], addr);
        }
        #pragma unroll
        for (int mt = 0; mt < 4; mt++)
            #pragma unroll
            for (int nt = 0; nt < 4; nt++)
                mma_bf16(acc[mt][nt], af[mt], bf[nt]);
    }

    // ---- epilogue: fragment layout rows = lane>>2 (+8), cols = 2*(lane&3) (+1) ----
    int lr = lane >> 2;          // 0..7
    int lc = (lane & 3) * 2;     // 0,2,4,6

    float aq[4][2], bq[4][2];
    #pragma unroll
    for (int mt = 0; mt < 4; mt++) {
        aq[mt][0] = asq[R0 + mt * 16 + lr];
        aq[mt][1] = asq[R0 + mt * 16 + lr + 8];
    }
    #pragma unroll
    for (int nt = 0; nt < 4; nt++) {
        bq[nt][0] = bsq[C0 + nt * 8 + lc];
        bq[nt][1] = bsq[C0 + nt * 8 + lc + 1];
    }

    float rm[4][2];              // row-max per (mt, row-half)
    float cm[4][2];              // col-max per (nt, col-parity)
    #pragma unroll
    for (int i = 0; i < 4; i++) { rm[i][0] = rm[i][1] = NEGINF; cm[i][0] = cm[i][1] = NEGINF; }

    #pragma unroll
    for (int mt = 0; mt < 4; mt++) {
        int r0 = R0 + mt * 16 + lr;
        #pragma unroll
        for (int nt = 0; nt < 4; nt++) {
            int c0 = C0 + nt * 8 + lc;
            #pragma unroll
            for (int rg = 0; rg < 4; rg++) {
                int rr = r0 + (rg >> 1) * 8;           // row for this reg
                int cc = c0 + (rg & 1);                // col for this reg
                float a = acc[mt][nt][rg];
                float vr = fmaf(2.f, a, -bq[nt][rg & 1]);
                float vc = fmaf(2.f, a, -aq[mt][rg >> 1]);
                if (diag && rr == cc) { vr = NEGINF; vc = NEGINF; }
                rm[mt][rg >> 1] = fmaxf(rm[mt][rg >> 1], vr);
                cm[nt][rg & 1]  = fmaxf(cm[nt][rg & 1], vc);
            }
        }
    }

    // row-max: reduce across lanes 0..3 of each row group (lane&3)
    #pragma unroll
    for (int mt = 0; mt < 4; mt++)
        #pragma unroll
        for (int h = 0; h < 2; h++) {
            float v = rm[mt][h];
            v = fmaxf(v, __shfl_xor_sync(0xffffffffu, v, 1));
            v = fmaxf(v, __shfl_xor_sync(0xffffffffu, v, 2));
            rm[mt][h] = v;
        }
    // col-max: reduce across row groups (xor 4, 8, 16)
    #pragma unroll
    for (int nt = 0; nt < 4; nt++)
        #pragma unroll
        for (int h = 0; h < 2; h++) {
            float v = cm[nt][h];
            v = fmaxf(v, __shfl_xor_sync(0xffffffffu, v, 4));
            v = fmaxf(v, __shfl_xor_sync(0xffffffffu, v, 8));
            v = fmaxf(v, __shfl_xor_sync(0xffffffffu, v, 16));
            cm[nt][h] = v;
        }

    float* rred = (float*)(sm + SM_RRED);
    float* cred = (float*)(sm + SM_CRED);
    if ((lane & 3) == 0) {
        #pragma unroll
        for (int mt = 0; mt < 4; mt++) {
            rred[(R0 + mt * 16 + lr) * 4 + warp_n]     = rm[mt][0];
            rred[(R0 + mt * 16 + lr + 8) * 4 + warp_n] = rm[mt][1];
        }
    }
    if (lane < 4) {
        #pragma unroll
        for (int nt = 0; nt < 4; nt++) {
            cred[(C0 + nt * 8 + lc) * 2 + warp_m]     = cm[nt][0];
            cred[(C0 + nt * 8 + lc + 1) * 2 + warp_m] = cm[nt][1];
        }
    }
    __syncthreads();
    if (tid < 128) {
        float m = fmaxf(fmaxf(rred[tid * 4 + 0], rred[tid * 4 + 1]),
                        fmaxf(rred[tid * 4 + 2], rred[tid * 4 + 3]));
        atomicMax(&g_rowmax[bi * 128 + tid], fenc(m));
    } else {
        int t = tid - 128;
        float m = fmaxf(cred[t * 2 + 0], cred[t * 2 + 1]);
        atomicMax(&g_rowmax[bj * 128 + t], fenc(m));
    }
}

// ---------------- K3: screen rows; default lse = 0 ----------------
__global__ void k3_screen(const float* __restrict__ phi) {
    int i = blockIdx.x * blockDim.x + threadIdx.x;
    if (i >= N) return;
    float var = softplus_var(phi);
    float m = fdec(g_rowmax[i]);
    float zmax = fminf((m - g_sq[i]) * (0.5f / var), 0.f);
    g_lse[i] = 0.f;
    if (zmax > -35.f) {
        int k = atomicAdd(&g_flagcnt, 1);
        g_flaglist[k] = i;
    }
}

// ---------------- K4: exact fp32 fallback for flagged rows ----------------
__global__ void k4_exact(const float* __restrict__ x, const float* __restrict__ phi) {
    __shared__ float xi[D];
    __shared__ float part[256];
    int nf = g_flagcnt;
    float var = softplus_var(phi);
    float half_inv = 0.5f / var;
    for (int f = blockIdx.x; f < nf; f += gridDim.x) {
        int i = g_flaglist[f];
        if (threadIdx.x < D) xi[threadIdx.x] = x[(size_t)i * D + threadIdx.x];
        __syncthreads();
        float sqi = g_sq[i];
        float s = 0.f;
        for (int j = threadIdx.x; j < N; j += blockDim.x) {
            const float* xj = x + (size_t)j * D;
            float dot = 0.f;
            #pragma unroll 8
            for (int k = 0; k < D; k++) dot += xi[k] * xj[k];
            float d2 = fmaxf(sqi + g_sq[j] - 2.f * dot, 0.f);
            s += expf(-d2 * half_inv);
        }
        part[threadIdx.x] = s;
        __syncthreads();
        for (int o = 128; o; o >>= 1) {
            if (threadIdx.x < o) part[threadIdx.x] += part[threadIdx.x + o];
            __syncthreads();
        }
        if (threadIdx.x == 0) g_lse[i] = logf(part[0]);
        __syncthreads();
    }
}

// ---------------- K5: reduce -> IXT ----------------
__global__ void k5_reduce(float* __restrict__ out_scalar) {
    __shared__ float part[256];
    float s = 0.f;
    for (int i = threadIdx.x; i < N; i += 256) s += g_lse[i];
    part[threadIdx.x] = s;
    __syncthreads();
    for (int o = 128; o; o >>= 1) {
        if (threadIdx.x < o) part[threadIdx.x] += part[threadIdx.x + o];
        __syncthreads();
    }
    if (threadIdx.x == 0) {
        float kde = part[0] / (float)N;
        float ixt = (logf((float)N) - kde) * 1.4426950408889634f;
        *out_scalar = ixt;
    }
}

// ---------------- launch ----------------
extern "C" void kernel_launch(void* const* d_in, const int* in_sizes, int n_in,
                              void* d_out, int out_size) {
    const float* x     = (const float*)d_in[0];
    const float* phi   = (const float*)d_in[1];
    const float* noise = (const float*)d_in[2];
    float* out = (float*)d_out;

    static bool attr_done = false;
    if (!attr_done) {
        cudaFuncSetAttribute(k2_gram_mma, cudaFuncAttributeMaxDynamicSharedMemorySize, SM_TOTAL);
        attr_done = true;
    }

    k1_rows<<<N, 128>>>(x, phi, noise, out);
    k2_gram_mma<<<NB * (NB + 1) / 2, 256, SM_TOTAL>>>();
    k3_screen<<<(N + 255) / 256, 256>>>(phi);
    k4_exact<<<64, 256>>>(x, phi);
    k5_reduce<<<1, 256>>>(out + out_size - 1);
}

// round 4
// speedup vs baseline: 4.6484x; 1.2281x over previous
#include <cuda_runtime.h>
#include <cuda_bf16.h>
#include <cuda_fp8.h>
#include <math.h>
#include <stdint.h>

#define N 8192
#define D 128
#define NB 64                 // N / 128
#define ENC_NEGINF 0x007FFFFFu
#define NEGINF __int_as_float(0xff800000)

// ---------------- scratch (static __device__, no allocation) ----------------
__device__ unsigned g_rowmax[N];   // encoded-float max_{j!=i} (2*G_ij - sq_j)
__device__ float    g_sq[N];
__device__ float    g_lse[N];
__device__ int      g_flaglist[N];
__device__ int      g_flagcnt;
__device__ int      g_bar[2];
__device__ __align__(16) unsigned char g_x8[N * D];   // fp8 e4m3 copy of x (1 MB)

// ---------------- helpers ----------------
__device__ __forceinline__ uint32_t smem_u32(const void* p) {
    uint32_t a;
    asm("{ .reg .u64 t; cvta.to.shared.u64 t, %1; cvt.u32.u64 %0, t; }" : "=r"(a) : "l"(p));
    return a;
}
__device__ __forceinline__ float softplus_var(const float* __restrict__ phi) {
    float p = *phi;
    return (p > 20.f) ? p : log1pf(expf(p));
}
// order-preserving float<->uint encoding for atomicMax
__device__ __forceinline__ unsigned fenc(float f) {
    unsigned u = __float_as_uint(f);
    return (u & 0x80000000u) ? ~u : (u | 0x80000000u);
}
__device__ __forceinline__ float fdec(unsigned e) {
    return (e & 0x80000000u) ? __uint_as_float(e & 0x7FFFFFFFu)
                             : __uint_as_float(~e);
}

__device__ __forceinline__ void ldsm_x4(uint32_t& r0, uint32_t& r1, uint32_t& r2, uint32_t& r3,
                                        uint32_t addr) {
    asm volatile("ldmatrix.sync.aligned.m8n8.x4.shared.b16 {%0,%1,%2,%3}, [%4];"
                 : "=r"(r0), "=r"(r1), "=r"(r2), "=r"(r3) : "r"(addr));
}
__device__ __forceinline__ void ldsm_x2(uint32_t& r0, uint32_t& r1, uint32_t addr) {
    asm volatile("ldmatrix.sync.aligned.m8n8.x2.shared.b16 {%0,%1}, [%2];"
                 : "=r"(r0), "=r"(r1) : "r"(addr));
}
// fp8 e4m3 mma: D[16x8] += A[16x32] * B[32x8]
__device__ __forceinline__ void mma_fp8(float* d, const uint32_t* a, const uint32_t* b) {
    asm volatile(
        "mma.sync.aligned.m16n8k32.row.col.f32.e4m3.e4m3.f32 "
        "{%0,%1,%2,%3}, {%4,%5,%6,%7}, {%8,%9}, {%0,%1,%2,%3};"
        : "+f"(d[0]), "+f"(d[1]), "+f"(d[2]), "+f"(d[3])
        : "r"(a[0]), "r"(a[1]), "r"(a[2]), "r"(a[3]), "r"(b[0]), "r"(b[1]));
}

// ---------------- K1: out = x + var*noise ; sq ; fp8 copy ; init (warp per row) ----------------
__global__ __launch_bounds__(256) void k1_rows(const float* __restrict__ x,
                                               const float* __restrict__ phi,
                                               const float* __restrict__ noise,
                                               float* __restrict__ out) {
    int gtid = blockIdx.x * 256 + threadIdx.x;
    int r = gtid >> 5;             // warp = row; grid 1024 x 256 -> 8192 rows
    int lane = gtid & 31;
    float var = softplus_var(phi);

    float4 xv = ((const float4*)x)[r * 32 + lane];
    float4 nv = ((const float4*)noise)[r * 32 + lane];
    float4 ov;
    ov.x = fmaf(var, nv.x, xv.x); ov.y = fmaf(var, nv.y, xv.y);
    ov.z = fmaf(var, nv.z, xv.z); ov.w = fmaf(var, nv.w, xv.w);
    ((float4*)out)[r * 32 + lane] = ov;

    uchar4 q;
    q.x = (unsigned char)__nv_cvt_float_to_fp8(xv.x, __NV_SATFINITE, __NV_E4M3);
    q.y = (unsigned char)__nv_cvt_float_to_fp8(xv.y, __NV_SATFINITE, __NV_E4M3);
    q.z = (unsigned char)__nv_cvt_float_to_fp8(xv.z, __NV_SATFINITE, __NV_E4M3);
    q.w = (unsigned char)__nv_cvt_float_to_fp8(xv.w, __NV_SATFINITE, __NV_E4M3);
    ((uchar4*)g_x8)[r * 32 + lane] = q;

    float s = xv.x * xv.x + xv.y * xv.y + xv.z * xv.z + xv.w * xv.w;
    #pragma unroll
    for (int o = 16; o; o >>= 1) s += __shfl_xor_sync(0xffffffffu, s, o);
    if (lane == 0) {
        g_sq[r] = s;
        g_rowmax[r] = ENC_NEGINF;
    }
    if (gtid == 0) { g_flagcnt = 0; g_bar[0] = 0; g_bar[1] = 0; }
}

// ---------------- K2: fp8 mma.sync Gram, upper triangle, row/col maxes ----------------
// tile: 128 rows x 128 fp8 bytes, padded row stride 144 B (conflict-free ldmatrix)
#define ROWB 144

__global__ __launch_bounds__(256, 2)
void k2_gram_mma() {
    __shared__ __align__(16) unsigned char smA[128 * ROWB];
    __shared__ __align__(16) unsigned char smB[128 * ROWB];
    __shared__ float asq[128], bsq[128];
    __shared__ float rred[128 * 4];
    __shared__ float cred[128 * 2];

    uint32_t sa = smem_u32(smA);
    uint32_t sbm = smem_u32(smB);
    int tid = threadIdx.x;
    int wid = tid >> 5, lane = tid & 31;
    int warp_m = wid >> 2;          // 0..1  (64-row band)
    int warp_n = wid & 3;           // 0..3  (32-col band)

    // triangular block decode: b -> (bi, bj), bi <= bj
    int b = blockIdx.x;
    int bi = 0, rem = b;
    while (rem >= NB - bi) { rem -= NB - bi; bi++; }
    int bj = bi + rem;
    bool diag = (bi == bj);

    // ---- load tiles (fp8, 128 B per row = 8 uint4) ----
    const uint4* Ag = (const uint4*)(g_x8 + (size_t)bi * 128 * D);
    const uint4* Bg = (const uint4*)(g_x8 + (size_t)bj * 128 * D);
    #pragma unroll
    for (int it = 0; it < 4; it++) {
        int q = it * 256 + tid;             // 0..1023
        int row = q >> 3, seg = q & 7;
        uint32_t off = (uint32_t)row * ROWB + (uint32_t)seg * 16;
        *(uint4*)(smA + off) = Ag[q];
        *(uint4*)(smB + off) = Bg[q];
    }
    if (tid < 128) asq[tid] = g_sq[bi * 128 + tid];
    else           bsq[tid - 128] = g_sq[bj * 128 + tid - 128];
    __syncthreads();

    // ---- mma mainloop: warp tile 64x32, K=128 (4 k-steps of 32) ----
    int R0 = warp_m * 64;
    int C0 = warp_n * 32;
    float acc[4][4][4];
    #pragma unroll
    for (int mt = 0; mt < 4; mt++)
        #pragma unroll
        for (int nt = 0; nt < 4; nt++)
            #pragma unroll
            for (int r = 0; r < 4; r++) acc[mt][nt][r] = 0.f;

    // ldmatrix lane addressing (16-byte k-slabs)
    uint32_t a_row = (uint32_t)(R0 + (lane & 15));
    uint32_t a_kb  = (uint32_t)((lane >> 4) * 16);
    uint32_t b_row = (uint32_t)(C0 + (lane & 7));
    uint32_t b_kb  = (uint32_t)(((lane >> 3) & 1) * 16);

    #pragma unroll
    for (int kt = 0; kt < 4; kt++) {
        uint32_t kbase = (uint32_t)kt * 32;   // 32 fp8 bytes per k-step
        uint32_t af[4][4];
        #pragma unroll
        for (int mt = 0; mt < 4; mt++) {
            uint32_t addr = sa + (a_row + mt * 16) * ROWB + kbase + a_kb;
            ldsm_x4(af[mt][0], af[mt][1], af[mt][2], af[mt][3], addr);
        }
        uint32_t bf[4][2];
        #pragma unroll
        for (int nt = 0; nt < 4; nt++) {
            uint32_t addr = sbm + (b_row + nt * 8) * ROWB + kbase + b_kb;
            ldsm_x2(bf[nt][0], bf[nt][1], addr);
        }
        #pragma unroll
        for (int mt = 0; mt < 4; mt++)
            #pragma unroll
            for (int nt = 0; nt < 4; nt++)
                mma_fp8(acc[mt][nt], af[mt], bf[nt]);
    }

    // ---- epilogue: fragment rows = lane>>2 (+8), cols = 2*(lane&3) (+1) ----
    int lr = lane >> 2;
    int lc = (lane & 3) * 2;

    float aq[4][2], bq[4][2];
    #pragma unroll
    for (int mt = 0; mt < 4; mt++) {
        aq[mt][0] = asq[R0 + mt * 16 + lr];
        aq[mt][1] = asq[R0 + mt * 16 + lr + 8];
    }
    #pragma unroll
    for (int nt = 0; nt < 4; nt++) {
        bq[nt][0] = bsq[C0 + nt * 8 + lc];
        bq[nt][1] = bsq[C0 + nt * 8 + lc + 1];
    }

    float rm[4][2];
    float cm[4][2];
    #pragma unroll
    for (int i = 0; i < 4; i++) { rm[i][0] = rm[i][1] = NEGINF; cm[i][0] = cm[i][1] = NEGINF; }

    #pragma unroll
    for (int mt = 0; mt < 4; mt++) {
        int r0 = R0 + mt * 16 + lr;
        #pragma unroll
        for (int nt = 0; nt < 4; nt++) {
            int c0 = C0 + nt * 8 + lc;
            #pragma unroll
            for (int rg = 0; rg < 4; rg++) {
                int rr = r0 + (rg >> 1) * 8;
                int cc = c0 + (rg & 1);
                float a = acc[mt][nt][rg];
                float vr = fmaf(2.f, a, -bq[nt][rg & 1]);
                float vc = fmaf(2.f, a, -aq[mt][rg >> 1]);
                if (diag && rr == cc) { vr = NEGINF; vc = NEGINF; }
                rm[mt][rg >> 1] = fmaxf(rm[mt][rg >> 1], vr);
                cm[nt][rg & 1]  = fmaxf(cm[nt][rg & 1], vc);
            }
        }
    }

    #pragma unroll
    for (int mt = 0; mt < 4; mt++)
        #pragma unroll
        for (int h = 0; h < 2; h++) {
            float v = rm[mt][h];
            v = fmaxf(v, __shfl_xor_sync(0xffffffffu, v, 1));
            v = fmaxf(v, __shfl_xor_sync(0xffffffffu, v, 2));
            rm[mt][h] = v;
        }
    #pragma unroll
    for (int nt = 0; nt < 4; nt++)
        #pragma unroll
        for (int h = 0; h < 2; h++) {
            float v = cm[nt][h];
            v = fmaxf(v, __shfl_xor_sync(0xffffffffu, v, 4));
            v = fmaxf(v, __shfl_xor_sync(0xffffffffu, v, 8));
            v = fmaxf(v, __shfl_xor_sync(0xffffffffu, v, 16));
            cm[nt][h] = v;
        }

    if ((lane & 3) == 0) {
        #pragma unroll
        for (int mt = 0; mt < 4; mt++) {
            rred[(R0 + mt * 16 + lr) * 4 + warp_n]     = rm[mt][0];
            rred[(R0 + mt * 16 + lr + 8) * 4 + warp_n] = rm[mt][1];
        }
    }
    if (lane < 4) {
        #pragma unroll
        for (int nt = 0; nt < 4; nt++) {
            cred[(C0 + nt * 8 + lc) * 2 + warp_m]     = cm[nt][0];
            cred[(C0 + nt * 8 + lc + 1) * 2 + warp_m] = cm[nt][1];
        }
    }
    __syncthreads();
    if (tid < 128) {
        float m = fmaxf(fmaxf(rred[tid * 4 + 0], rred[tid * 4 + 1]),
                        fmaxf(rred[tid * 4 + 2], rred[tid * 4 + 3]));
        atomicMax(&g_rowmax[bi * 128 + tid], fenc(m));
    } else {
        int t = tid - 128;
        float m = fmaxf(cred[t * 2 + 0], cred[t * 2 + 1]);
        atomicMax(&g_rowmax[bj * 128 + t], fenc(m));
    }
}

// ---------------- fused tail: screen -> exact fallback -> reduce (64 blocks) ----------------
#define TAIL_BLOCKS 64
__device__ __forceinline__ void grid_bar(int idx) {
    __syncthreads();
    if (threadIdx.x == 0) {
        __threadfence();
        atomicAdd(&g_bar[idx], 1);
        while (*(volatile int*)&g_bar[idx] < TAIL_BLOCKS) {}
    }
    __syncthreads();
}

__global__ __launch_bounds__(256) void k_tail(const float* __restrict__ x,
                                              const float* __restrict__ phi,
                                              float* __restrict__ out_scalar) {
    __shared__ float xi[D];
    __shared__ float part[256];
    int tid = threadIdx.x;
    float var = softplus_var(phi);
    float half_inv = 0.5f / var;

    // ---- phase 1: screen ----
    if (tid < 128) {
        int i = blockIdx.x * 128 + tid;
        float m = fdec(g_rowmax[i]);
        float zmax = fminf((m - g_sq[i]) * half_inv, 0.f);
        g_lse[i] = 0.f;
        if (zmax > -35.f) {
            int k = atomicAdd(&g_flagcnt, 1);
            g_flaglist[k] = i;
        }
    }
    grid_bar(0);

    // ---- phase 2: exact fp32 fallback for flagged rows ----
    int nf = *(volatile int*)&g_flagcnt;
    for (int f = blockIdx.x; f < nf; f += TAIL_BLOCKS) {
        int i = g_flaglist[f];
        if (tid < D) xi[tid] = x[(size_t)i * D + tid];
        __syncthreads();
        float sqi = g_sq[i];
        float s = 0.f;
        for (int j = tid; j < N; j += 256) {
            const float* xj = x + (size_t)j * D;
            float dot = 0.f;
            #pragma unroll 8
            for (int k = 0; k < D; k++) dot += xi[k] * xj[k];
            float d2 = fmaxf(sqi + g_sq[j] - 2.f * dot, 0.f);
            s += expf(-d2 * half_inv);
        }
        part[tid] = s;
        __syncthreads();
        for (int o = 128; o; o >>= 1) {
            if (tid < o) part[tid] += part[tid + o];
            __syncthreads();
        }
        if (tid == 0) g_lse[i] = logf(part[0]);
        __syncthreads();
    }
    grid_bar(1);

    // ---- phase 3: reduce -> IXT (block 0) ----
    if (blockIdx.x == 0) {
        float s = 0.f;
        for (int i = tid; i < N; i += 256) s += g_lse[i];
        part[tid] = s;
        __syncthreads();
        for (int o = 128; o; o >>= 1) {
            if (tid < o) part[tid] += part[tid + o];
            __syncthreads();
        }
        if (tid == 0) {
            float kde = part[0] / (float)N;
            float ixt = (logf((float)N) - kde) * 1.4426950408889634f;
            *out_scalar = ixt;
        }
    }
}

// ---------------- launch ----------------
extern "C" void kernel_launch(void* const* d_in, const int* in_sizes, int n_in,
                              void* d_out, int out_size) {
    const float* x     = (const float*)d_in[0];
    const float* phi   = (const float*)d_in[1];
    const float* noise = (const float*)d_in[2];
    float* out = (float*)d_out;

    k1_rows<<<N / 8, 256>>>(x, phi, noise, out);
    k2_gram_mma<<<NB * (NB + 1) / 2, 256>>>();
    k_tail<<<TAIL_BLOCKS, 256>>>(x, phi, out + out_size - 1);
}